// round 2
// baseline (speedup 1.0000x reference)
#include <cuda_runtime.h>

// Adaptive threshold spike encoding — single-wave, streaming-store version.
// x: [B=32, F=65536] f32.  out: [B=32, T=32, F=65536] f32.
// Each thread handles 8 feature-adjacent elements (two float4 = 32B contiguous),
// emits 32 timestep planes via evict-first streaming stores (__stcs).
// Grid = 1024 blocks x 256 threads = 262,144 threads -> one wave on 148 SMs.

#define TIMESTEPS 32
#define F_DIM 65536
#define F4_DIM (F_DIM / 4)      // 16384 float4 per feature row
#define RATE 0.1f
#define ONE_MINUS_RATE 0.9f
#define THR0 0.5f

__global__ void adaptive_threshold_kernel(const float4* __restrict__ x,
                                          float4* __restrict__ out) {
    int i = blockIdx.x * blockDim.x + threadIdx.x;   // float8 index: 0..262143

    // element index of lane 0 of this 8-element group
    int e  = i << 3;
    int b  = e >> 16;                  // / 65536
    int f4 = (e & (F_DIM - 1)) >> 2;   // first float4 slot within the feature row

    float4 xv0 = __ldcs(&x[2 * i]);
    float4 xv1 = __ldcs(&x[2 * i + 1]);

    float xx[8] = {xv0.x, xv0.y, xv0.z, xv0.w, xv1.x, xv1.y, xv1.z, xv1.w};
    float adapt[8], acc[8], thr[8];
#pragma unroll
    for (int l = 0; l < 8; l++) {
        adapt[l] = RATE * fabsf(xx[l]);
        acc[l]   = 0.0f;
        thr[l]   = THR0;
    }

    // out[b][t][f]: base of this (b, f4) column; stride F4_DIM float4 per timestep
    float4* ob = out + (size_t)b * (TIMESTEPS * F4_DIM) + f4;

#pragma unroll
    for (int t = 0; t < TIMESTEPS; t++) {
        float s[8];
#pragma unroll
        for (int l = 0; l < 8; l++) {
            acc[l] = acc[l] + xx[l];
            bool m = (acc[l] >= thr[l]);
            s[l]   = m ? 1.0f : 0.0f;
            acc[l] = m ? 0.0f : acc[l];
            thr[l] = thr[l] * ONE_MINUS_RATE + adapt[l];
        }
        float4 sv0, sv1;
        sv0.x = s[0]; sv0.y = s[1]; sv0.z = s[2]; sv0.w = s[3];
        sv1.x = s[4]; sv1.y = s[5]; sv1.z = s[6]; sv1.w = s[7];
        float4* p = ob + (size_t)t * F4_DIM;
        __stcs(p,     sv0);
        __stcs(p + 1, sv1);
    }
}

extern "C" void kernel_launch(void* const* d_in, const int* in_sizes, int n_in,
                              void* d_out, int out_size) {
    const float4* x = (const float4*)d_in[0];
    float4* out = (float4*)d_out;
    int n8 = in_sizes[0] / 8;          // 262,144 threads
    int threads = 256;
    int blocks = n8 / threads;         // 1024 blocks -> single wave
    adaptive_threshold_kernel<<<blocks, threads>>>(x, out);
}

// round 3
// speedup vs baseline: 1.9698x; 1.9698x over previous
#include <cuda_runtime.h>

// Adaptive threshold spike encoding — R1 structure + streaming-store policy.
// x: [B=32, F=65536] f32.  out: [B=32, T=32, F=65536] f32.
// One thread per float4 (524,288 threads, 32 regs, max occupancy).
// 32 coalesced STG.128 per thread, evict-first (__stcs) to keep L2 drained.

#define TIMESTEPS 32
#define F_DIM 65536
#define F4_DIM (F_DIM / 4)      // 16384 float4 per feature row
#define RATE 0.1f
#define ONE_MINUS_RATE 0.9f
#define THR0 0.5f

__global__ void adaptive_threshold_kernel(const float4* __restrict__ x,
                                          float4* __restrict__ out,
                                          int n4) {
    int i = blockIdx.x * blockDim.x + threadIdx.x;
    if (i >= n4) return;

    float4 xv = __ldcs(&x[i]);

    // element index -> (batch, feature4)
    int e  = i << 2;              // element index of lane 0 of this float4
    int b  = e >> 16;             // / 65536
    int f4 = (e & (F_DIM - 1)) >> 2;

    float xx[4] = {xv.x, xv.y, xv.z, xv.w};
    float adapt[4], acc[4], thr[4];
#pragma unroll
    for (int l = 0; l < 4; l++) {
        adapt[l] = RATE * fabsf(xx[l]);
        acc[l]   = 0.0f;
        thr[l]   = THR0;
    }

    // out[b][t][f] : base of this (b, f4) column, stride F4_DIM per timestep
    float4* ob = out + (size_t)b * (TIMESTEPS * F4_DIM) + f4;

#pragma unroll
    for (int t = 0; t < TIMESTEPS; t++) {
        float s[4];
#pragma unroll
        for (int l = 0; l < 4; l++) {
            acc[l] = acc[l] + xx[l];
            bool m = (acc[l] >= thr[l]);
            s[l]   = m ? 1.0f : 0.0f;
            acc[l] = m ? 0.0f : acc[l];
            thr[l] = thr[l] * ONE_MINUS_RATE + adapt[l];
        }
        float4 sv;
        sv.x = s[0]; sv.y = s[1]; sv.z = s[2]; sv.w = s[3];
        __stcs(ob + (size_t)t * F4_DIM, sv);
    }
}

extern "C" void kernel_launch(void* const* d_in, const int* in_sizes, int n_in,
                              void* d_out, int out_size) {
    const float4* x = (const float4*)d_in[0];
    float4* out = (float4*)d_out;
    int n4 = in_sizes[0] / 4;     // 524,288
    int threads = 256;
    int blocks = (n4 + threads - 1) / threads;   // 2048
    adaptive_threshold_kernel<<<blocks, threads>>>(x, out, n4);
}